// round 12
// baseline (speedup 1.0000x reference)
#include <cuda_runtime.h>
#include <cuda_bf16.h>
#include <stdint.h>

// ============================================================
// Legacy-HMMA (mma.sync m16n8k16 bf16) fused 3-layer MLP.
//  - bf16 2-way split (hi/lo); C += Ah*Bh + Al*Bh + Ah*Bl (fp32 accum)
//  - M=32 per warp (two 16-row blocks), 8 warps, TB=256.
//  - Weights staged in SMEM via cp.async (shared across all warps):
//      * W1: 3-slot x 8KB ring, chunk kg+2 prefetched while computing kg
//      * W2: full 64KB prefetched during layer-1 compute
//      * W3: copied into W2 buffer overlapped with epilogue 2
//    -> weight access is conflict-free LDS.128, no LDG scoreboard stalls.
//  - Hidden activations spilled to per-warp SMEM slab (conflict-free).
// ============================================================

#define W2OFF 141312u   // uint4 offsets into g_wbuf
#define W3OFF 227328u
__device__ uint4 g_wbuf[270336];   // 4.33 MB

struct NodeInfo { int gi, row, n, out, nb[6]; };
__constant__ NodeInfo c_nodes[21] = {
    {0,0,6, 0,{0,1,5,9,13,17}},
    {1,0,5, 5,{0,5,6,1,9,0}},
    {1,1,5, 9,{0,9,10,5,13,0}},
    {1,2,5,13,{0,13,14,9,17,0}},
    {2,0,4, 1,{0,1,2,5,0,0}},
    {2,1,4,17,{0,17,18,13,0,0}},
    {3,0,3, 2,{1,2,3,0,0,0}},
    {3,1,3, 3,{2,3,4,0,0,0}},
    {3,2,3, 6,{5,6,7,0,0,0}},
    {3,3,3, 7,{6,7,8,0,0,0}},
    {3,4,3,10,{9,10,11,0,0,0}},
    {3,5,3,11,{10,11,12,0,0,0}},
    {3,6,3,14,{13,14,15,0,0,0}},
    {3,7,3,15,{14,15,16,0,0,0}},
    {3,8,3,18,{17,18,19,0,0,0}},
    {3,9,3,19,{18,19,20,0,0,0}},
    {4,0,2, 4,{3,4,0,0,0,0}},
    {4,1,2, 8,{7,8,0,0,0,0}},
    {4,2,2,12,{11,12,0,0,0,0}},
    {4,3,2,16,{15,16,0,0,0,0}},
    {4,4,2,20,{19,20,0,0,0,0}},
};
__constant__ int c_offs1[21] = {0,6,11,16,21,25,29,32,35,38,41,44,47,50,53,56,59,61,63,65,67};

struct WPtrs { const float* w1[5]; const float* w2[5]; const float* w3[5]; };
struct BPtrs { const float* b1[5]; const float* b2[5]; const float* b3[5]; };

__device__ __forceinline__ void hilo2(float f0, float f1, uint32_t& hi, uint32_t& lo) {
    __nv_bfloat16 h0 = __float2bfloat16(f0), h1 = __float2bfloat16(f1);
    hi = (uint32_t)__bfloat16_as_ushort(h0) | ((uint32_t)__bfloat16_as_ushort(h1) << 16);
    float r0 = f0 - __bfloat162float(h0), r1 = f1 - __bfloat162float(h1);
    __nv_bfloat16 l0 = __float2bfloat16(r0), l1 = __float2bfloat16(r1);
    lo = (uint32_t)__bfloat16_as_ushort(l0) | ((uint32_t)__bfloat16_as_ushort(l1) << 16);
}

__device__ __forceinline__ void mma_bf16(float* c, const uint32_t* a,
                                         uint32_t b0, uint32_t b1) {
    asm volatile(
        "mma.sync.aligned.m16n8k16.row.col.f32.bf16.bf16.f32 "
        "{%0,%1,%2,%3}, {%4,%5,%6,%7}, {%8,%9}, {%0,%1,%2,%3};"
        : "+f"(c[0]), "+f"(c[1]), "+f"(c[2]), "+f"(c[3])
        : "r"(a[0]), "r"(a[1]), "r"(a[2]), "r"(a[3]), "r"(b0), "r"(b1));
}

__device__ __forceinline__ void cp16(void* s, const void* g) {
    asm volatile("cp.async.cg.shared.global [%0], [%1], 16;"
                 :: "r"((uint32_t)__cvta_generic_to_shared(s)), "l"(g));
}
__device__ __forceinline__ void cp_commit() {
    asm volatile("cp.async.commit_group;" ::: "memory");
}
template<int N> __device__ __forceinline__ void cp_wait() {
    asm volatile("cp.async.wait_group %0;" :: "n"(N) : "memory");
}

// ============================================================
// prep kernel: split weights into bf16 hi/lo B-fragment images.
// ============================================================
__global__ void prep_kernel(WPtrs wp)
{
    const int node = blockIdx.x, tid = threadIdx.x;
    const NodeInfo& nd = c_nodes[node];

    {   // W1: [n*64, 128], NT=16, KT=4n
        const float* W = wp.w1[nd.gi] + (size_t)nd.row * nd.n * 64 * 128;
        uint4* dst = g_wbuf + (size_t)c_offs1[node] * 2048;
        const int tot = nd.n * 2048;
        for (int i = tid; i < tot; i += blockDim.x) {
            int lane = i & 31, idx = i >> 5, nt = idx & 15, kt = idx >> 4;
            int g = lane >> 2, t = lane & 3;
            int n = nt * 8 + g, k0 = kt * 16 + 2 * t;
            float a0 = W[(size_t)k0 * 128 + n],       a1 = W[(size_t)(k0 + 1) * 128 + n];
            float a2 = W[(size_t)(k0 + 8) * 128 + n], a3 = W[(size_t)(k0 + 9) * 128 + n];
            uint4 v;
            hilo2(a0, a1, v.x, v.z);
            hilo2(a2, a3, v.y, v.w);
            dst[i] = v;
        }
    }
    {   // W2: [128,128], NT=16, KT=8
        const float* W = wp.w2[nd.gi] + (size_t)nd.row * 128 * 128;
        uint4* dst = g_wbuf + W2OFF + (size_t)node * 4096;
        for (int i = tid; i < 4096; i += blockDim.x) {
            int lane = i & 31, idx = i >> 5, nt = idx & 15, kt = idx >> 4;
            int g = lane >> 2, t = lane & 3;
            int n = nt * 8 + g, k0 = kt * 16 + 2 * t;
            float a0 = W[(size_t)k0 * 128 + n],       a1 = W[(size_t)(k0 + 1) * 128 + n];
            float a2 = W[(size_t)(k0 + 8) * 128 + n], a3 = W[(size_t)(k0 + 9) * 128 + n];
            uint4 v;
            hilo2(a0, a1, v.x, v.z);
            hilo2(a2, a3, v.y, v.w);
            dst[i] = v;
        }
    }
    {   // W3: [128,64], NT=8, KT=8
        const float* W = wp.w3[nd.gi] + (size_t)nd.row * 128 * 64;
        uint4* dst = g_wbuf + W3OFF + (size_t)node * 2048;
        for (int i = tid; i < 2048; i += blockDim.x) {
            int lane = i & 31, idx = i >> 5, nt = idx & 7, kt = idx >> 3;
            int g = lane >> 2, t = lane & 3;
            int n = nt * 8 + g, k0 = kt * 16 + 2 * t;
            float a0 = W[(size_t)k0 * 64 + n],       a1 = W[(size_t)(k0 + 1) * 64 + n];
            float a2 = W[(size_t)(k0 + 8) * 64 + n], a3 = W[(size_t)(k0 + 9) * 64 + n];
            uint4 v;
            hilo2(a0, a1, v.x, v.z);
            hilo2(a2, a3, v.y, v.w);
            dst[i] = v;
        }
    }
}

// ============================================================
// main kernel: 8 warps, M=32/warp, TB=256. grid = (21, B/256).
// SMEM (uint4 units):
//   [0, 8192)       hidden spill: wid*1024 + ((m*8+kt)*2+plane)*32 + lane
//   [8192, 12288)   W2/W3 buffer (64KB)
//   [12288, 13824)  W1 ring: 3 slots x 512
// ============================================================
#define SPILL_OFF  0
#define W2BUF_OFF  8192
#define RING_OFF   12288
#define SMEM_BYTES (13824 * 16)   // 221184

__global__ void __launch_bounds__(256, 1)
mp_mma_kernel(const float* __restrict__ x, BPtrs bp, float* __restrict__ out)
{
    extern __shared__ uint4 smem[];
    uint4* spill = smem + SPILL_OFF;
    uint4* w2buf = smem + W2BUF_OFF;
    uint4* ring  = smem + RING_OFF;

    const int tid = threadIdx.x;
    const int wid = tid >> 5, lane = tid & 31;
    const int g = lane >> 2, t = lane & 3;
    const int node = blockIdx.x;
    const NodeInfo& nd = c_nodes[node];
    const int r0 = blockIdx.y * 256 + wid * 32 + g;

    uint4* hslab = spill + wid * 1024 + lane;

    const uint4* W1g = g_wbuf + (size_t)c_offs1[node] * 2048;
    const uint4* W2g = g_wbuf + W2OFF + (size_t)node * 4096;
    const uint4* W3g = g_wbuf + W3OFF + (size_t)node * 2048;
    const int NK = nd.n * 4;

    // ---- prologue: async copies ----
    // group 1: full W2 (lands during layer-1 compute)
    #pragma unroll
    for (int j = 0; j < 16; ++j)
        cp16(&w2buf[tid + j * 256], &W2g[tid + j * 256]);
    cp_commit();
    // group 2: W1 chunk 0 ; group 3: W1 chunk 1
    cp16(&ring[tid],       &W1g[tid]);
    cp16(&ring[tid + 256], &W1g[tid + 256]);
    cp_commit();
    cp16(&ring[512 + tid],       &W1g[512 + tid]);
    cp16(&ring[512 + tid + 256], &W1g[512 + tid + 256]);
    cp_commit();

    float C[2][16][4];
    #pragma unroll
    for (int m = 0; m < 2; ++m)
        #pragma unroll
        for (int i = 0; i < 16; ++i)
            C[m][i][0] = C[m][i][1] = C[m][i][2] = C[m][i][3] = 0.f;

    // ---------------- layer 1 ----------------
    // x prefetch for kg=0
    float2 px[2][4];
    {
        const float* pb = x + (size_t)r0 * 1344 + nd.nb[0] * 64 + 2 * t;
        #pragma unroll
        for (int m = 0; m < 2; ++m) {
            const float* p = pb + (size_t)m * 16 * 1344;
            px[m][0] = *(const float2*)(p);
            px[m][1] = *(const float2*)(p + 8 * 1344);
            px[m][2] = *(const float2*)(p + 8);
            px[m][3] = *(const float2*)(p + 8 * 1344 + 8);
        }
    }

    for (int kg = 0; kg < NK; ++kg) {
        // chunk kg resident after: wait (own FIFO) + barrier (others' copies)
        cp_wait<1>();
        __syncthreads();
        // issue chunk kg+2 into slot (kg+2)%3 (held chunk kg-1: consumed)
        {
            int c = kg + 2;
            if (c < NK) {
                uint4* dst = ring + (c % 3) * 512;
                const uint4* src = W1g + (size_t)c * 512;
                cp16(&dst[tid], &src[tid]);
                cp16(&dst[tid + 256], &src[tid + 256]);
            }
            cp_commit();
        }
        // convert current x, then prefetch next
        uint32_t ah[2][4], al[2][4];
        #pragma unroll
        for (int m = 0; m < 2; ++m) {
            hilo2(px[m][0].x, px[m][0].y, ah[m][0], al[m][0]);
            hilo2(px[m][1].x, px[m][1].y, ah[m][1], al[m][1]);
            hilo2(px[m][2].x, px[m][2].y, ah[m][2], al[m][2]);
            hilo2(px[m][3].x, px[m][3].y, ah[m][3], al[m][3]);
        }
        int nxt = kg + 1;
        if (nxt < NK) {
            const float* pb = x + (size_t)r0 * 1344 + nd.nb[nxt >> 2] * 64
                              + (nxt & 3) * 16 + 2 * t;
            #pragma unroll
            for (int m = 0; m < 2; ++m) {
                const float* p = pb + (size_t)m * 16 * 1344;
                px[m][0] = *(const float2*)(p);
                px[m][1] = *(const float2*)(p + 8 * 1344);
                px[m][2] = *(const float2*)(p + 8);
                px[m][3] = *(const float2*)(p + 8 * 1344 + 8);
            }
        }
        const uint4* wr = ring + (kg % 3) * 512 + lane;
        #pragma unroll
        for (int nt = 0; nt < 16; ++nt) {
            uint4 b = wr[nt * 32];
            #pragma unroll
            for (int m = 0; m < 2; ++m) {
                mma_bf16(C[m][nt], ah[m], b.x, b.y);
                mma_bf16(C[m][nt], al[m], b.x, b.y);
                mma_bf16(C[m][nt], ah[m], b.z, b.w);
            }
        }
    }

    // epilogue 1: bias + relu -> smem spill (warp-private)
    {
        const float* B1 = bp.b1[nd.gi] + nd.row * 128;
        #pragma unroll
        for (int nt = 0; nt < 16; ++nt) {
            float2 bv = *(const float2*)(B1 + nt * 8 + 2 * t);
            const int kt = nt >> 1, h = nt & 1;
            #pragma unroll
            for (int m = 0; m < 2; ++m) {
                float v0 = fmaxf(C[m][nt][0] + bv.x, 0.f);
                float v1 = fmaxf(C[m][nt][1] + bv.y, 0.f);
                float v2 = fmaxf(C[m][nt][2] + bv.x, 0.f);
                float v3 = fmaxf(C[m][nt][3] + bv.y, 0.f);
                uint32_t h01, l01, h23, l23;
                hilo2(v0, v1, h01, l01);
                hilo2(v2, v3, h23, l23);
                uint2* dhi = (uint2*)(hslab + ((m * 8 + kt) * 2 + 0) * 32);
                uint2* dlo = (uint2*)(hslab + ((m * 8 + kt) * 2 + 1) * 32);
                dhi[h] = make_uint2(h01, h23);
                dlo[h] = make_uint2(l01, l23);
            }
        }
    }

    // ---------------- layer 2 ----------------
    cp_wait<0>();        // W2 buffer complete
    __syncthreads();

    #pragma unroll
    for (int m = 0; m < 2; ++m)
        #pragma unroll
        for (int i = 0; i < 16; ++i)
            C[m][i][0] = C[m][i][1] = C[m][i][2] = C[m][i][3] = 0.f;
    {
        #pragma unroll
        for (int kt = 0; kt < 8; ++kt) {
            uint32_t Ah[2][4], Al[2][4];
            #pragma unroll
            for (int m = 0; m < 2; ++m) {
                uint4 hv = hslab[((m * 8 + kt) * 2 + 0) * 32];
                uint4 lv = hslab[((m * 8 + kt) * 2 + 1) * 32];
                Ah[m][0]=hv.x; Ah[m][1]=hv.y; Ah[m][2]=hv.z; Ah[m][3]=hv.w;
                Al[m][0]=lv.x; Al[m][1]=lv.y; Al[m][2]=lv.z; Al[m][3]=lv.w;
            }
            const uint4* wr = w2buf + kt * 512 + lane;
            #pragma unroll
            for (int nt = 0; nt < 16; ++nt) {
                uint4 b = wr[nt * 32];
                #pragma unroll
                for (int m = 0; m < 2; ++m) {
                    mma_bf16(C[m][nt], Ah[m], b.x, b.y);
                    mma_bf16(C[m][nt], Al[m], b.x, b.y);
                    mma_bf16(C[m][nt], Ah[m], b.z, b.w);
                }
            }
        }
    }

    // all warps done reading W2 buffer -> stage W3 into it (overlap epilogue 2)
    __syncthreads();
    #pragma unroll
    for (int j = 0; j < 8; ++j)
        cp16(&w2buf[tid + j * 256], &W3g[tid + j * 256]);
    cp_commit();

    // epilogue 2 -> smem spill (overwrite; warp-private, overlaps W3 copy)
    {
        const float* B2 = bp.b2[nd.gi] + nd.row * 128;
        #pragma unroll
        for (int nt = 0; nt < 16; ++nt) {
            float2 bv = *(const float2*)(B2 + nt * 8 + 2 * t);
            const int kt = nt >> 1, h = nt & 1;
            #pragma unroll
            for (int m = 0; m < 2; ++m) {
                float v0 = fmaxf(C[m][nt][0] + bv.x, 0.f);
                float v1 = fmaxf(C[m][nt][1] + bv.y, 0.f);
                float v2 = fmaxf(C[m][nt][2] + bv.x, 0.f);
                float v3 = fmaxf(C[m][nt][3] + bv.y, 0.f);
                uint32_t h01, l01, h23, l23;
                hilo2(v0, v1, h01, l01);
                hilo2(v2, v3, h23, l23);
                uint2* dhi = (uint2*)(hslab + ((m * 8 + kt) * 2 + 0) * 32);
                uint2* dlo = (uint2*)(hslab + ((m * 8 + kt) * 2 + 1) * 32);
                dhi[h] = make_uint2(h01, h23);
                dlo[h] = make_uint2(l01, l23);
            }
        }
    }

    // ---------------- layer 3 ----------------
    cp_wait<0>();
    __syncthreads();

    #pragma unroll
    for (int m = 0; m < 2; ++m)
        #pragma unroll
        for (int i = 0; i < 8; ++i)
            C[m][i][0] = C[m][i][1] = C[m][i][2] = C[m][i][3] = 0.f;
    {
        #pragma unroll
        for (int kt = 0; kt < 8; ++kt) {
            uint32_t Ah[2][4], Al[2][4];
            #pragma unroll
            for (int m = 0; m < 2; ++m) {
                uint4 hv = hslab[((m * 8 + kt) * 2 + 0) * 32];
                uint4 lv = hslab[((m * 8 + kt) * 2 + 1) * 32];
                Ah[m][0]=hv.x; Ah[m][1]=hv.y; Ah[m][2]=hv.z; Ah[m][3]=hv.w;
                Al[m][0]=lv.x; Al[m][1]=lv.y; Al[m][2]=lv.z; Al[m][3]=lv.w;
            }
            const uint4* wr = w2buf + kt * 256 + lane;
            #pragma unroll
            for (int nt = 0; nt < 8; ++nt) {
                uint4 b = wr[nt * 32];
                #pragma unroll
                for (int m = 0; m < 2; ++m) {
                    mma_bf16(C[m][nt], Ah[m], b.x, b.y);
                    mma_bf16(C[m][nt], Al[m], b.x, b.y);
                    mma_bf16(C[m][nt], Ah[m], b.z, b.w);
                }
            }
        }
    }

    // output epilogue
    {
        const float* B3 = bp.b3[nd.gi] + nd.row * 64;
        #pragma unroll
        for (int m = 0; m < 2; ++m) {
            float* o0 = out + (size_t)(r0 + m * 16) * 1344 + nd.out * 64 + 2 * t;
            #pragma unroll
            for (int nt = 0; nt < 8; ++nt) {
                float2 bv = *(const float2*)(B3 + nt * 8 + 2 * t);
                *(float2*)(o0 + nt * 8) =
                    make_float2(C[m][nt][0] + bv.x, C[m][nt][1] + bv.y);
                *(float2*)(o0 + nt * 8 + 8 * 1344) =
                    make_float2(C[m][nt][2] + bv.x, C[m][nt][3] + bv.y);
            }
        }
    }
}

// ============================================================
extern "C" void kernel_launch(void* const* d_in, const int* in_sizes, int n_in,
                              void* d_out, int out_size)
{
    const float* x = (const float*)d_in[0];
    WPtrs wp; BPtrs bp;
    for (int g = 0; g < 5; ++g) {
        wp.w1[g] = (const float*)d_in[1 + 6*g + 0];
        bp.b1[g] = (const float*)d_in[1 + 6*g + 1];
        wp.w2[g] = (const float*)d_in[1 + 6*g + 2];
        bp.b2[g] = (const float*)d_in[1 + 6*g + 3];
        wp.w3[g] = (const float*)d_in[1 + 6*g + 4];
        bp.b3[g] = (const float*)d_in[1 + 6*g + 5];
    }
    int B = in_sizes[0] / (21 * 64);

    prep_kernel<<<21, 256>>>(wp);

    cudaFuncSetAttribute(mp_mma_kernel,
                         cudaFuncAttributeMaxDynamicSharedMemorySize, SMEM_BYTES);
    dim3 grid(21, B / 256);
    mp_mma_kernel<<<grid, 256, SMEM_BYTES>>>(x, bp, (float*)d_out);
}

// round 13
// speedup vs baseline: 1.3117x; 1.3117x over previous
#include <cuda_runtime.h>
#include <cuda_bf16.h>
#include <stdint.h>

// ============================================================
// Legacy-HMMA (mma.sync m16n8k16 bf16) fused 3-layer MLP.
//  - bf16 2-way split (hi/lo); C += Ah*Bh + Al*Bh + Ah*Bl (fp32 accum)
//  - M=32 per warp (two 16-row blocks): one weight LDG.128 feeds 6 MMAs.
//  - 128-thread CTAs (4 warps), __launch_bounds__(128,2):
//    2 CTAs/SM -> 4 warps/SMSP latency hiding, zero barriers in mainloop.
//  - Hidden activations in per-warp SMEM slab (lane-contiguous,
//    conflict-free; warp-private so no syncs).
//  - Weights pre-packed into lane-indexed uint4 fragment images
//    {b0h,b1h,b0l,b1l} (L1/L2-resident, shared by all warps).
// ============================================================

#define W2OFF 141312u   // uint4 offsets into g_wbuf
#define W3OFF 227328u
__device__ uint4 g_wbuf[270336];   // 4.33 MB

struct NodeInfo { int gi, row, n, out, nb[6]; };
__constant__ NodeInfo c_nodes[21] = {
    {0,0,6, 0,{0,1,5,9,13,17}},
    {1,0,5, 5,{0,5,6,1,9,0}},
    {1,1,5, 9,{0,9,10,5,13,0}},
    {1,2,5,13,{0,13,14,9,17,0}},
    {2,0,4, 1,{0,1,2,5,0,0}},
    {2,1,4,17,{0,17,18,13,0,0}},
    {3,0,3, 2,{1,2,3,0,0,0}},
    {3,1,3, 3,{2,3,4,0,0,0}},
    {3,2,3, 6,{5,6,7,0,0,0}},
    {3,3,3, 7,{6,7,8,0,0,0}},
    {3,4,3,10,{9,10,11,0,0,0}},
    {3,5,3,11,{10,11,12,0,0,0}},
    {3,6,3,14,{13,14,15,0,0,0}},
    {3,7,3,15,{14,15,16,0,0,0}},
    {3,8,3,18,{17,18,19,0,0,0}},
    {3,9,3,19,{18,19,20,0,0,0}},
    {4,0,2, 4,{3,4,0,0,0,0}},
    {4,1,2, 8,{7,8,0,0,0,0}},
    {4,2,2,12,{11,12,0,0,0,0}},
    {4,3,2,16,{15,16,0,0,0,0}},
    {4,4,2,20,{19,20,0,0,0,0}},
};
__constant__ int c_offs1[21] = {0,6,11,16,21,25,29,32,35,38,41,44,47,50,53,56,59,61,63,65,67};

struct WPtrs { const float* w1[5]; const float* w2[5]; const float* w3[5]; };
struct BPtrs { const float* b1[5]; const float* b2[5]; const float* b3[5]; };

__device__ __forceinline__ void hilo2(float f0, float f1, uint32_t& hi, uint32_t& lo) {
    __nv_bfloat16 h0 = __float2bfloat16(f0), h1 = __float2bfloat16(f1);
    hi = (uint32_t)__bfloat16_as_ushort(h0) | ((uint32_t)__bfloat16_as_ushort(h1) << 16);
    float r0 = f0 - __bfloat162float(h0), r1 = f1 - __bfloat162float(h1);
    __nv_bfloat16 l0 = __float2bfloat16(r0), l1 = __float2bfloat16(r1);
    lo = (uint32_t)__bfloat16_as_ushort(l0) | ((uint32_t)__bfloat16_as_ushort(l1) << 16);
}

__device__ __forceinline__ void mma_bf16(float* c, const uint32_t* a,
                                         uint32_t b0, uint32_t b1) {
    asm volatile(
        "mma.sync.aligned.m16n8k16.row.col.f32.bf16.bf16.f32 "
        "{%0,%1,%2,%3}, {%4,%5,%6,%7}, {%8,%9}, {%0,%1,%2,%3};"
        : "+f"(c[0]), "+f"(c[1]), "+f"(c[2]), "+f"(c[3])
        : "r"(a[0]), "r"(a[1]), "r"(a[2]), "r"(a[3]), "r"(b0), "r"(b1));
}

// ============================================================
// prep kernel: split weights into bf16 hi/lo B-fragment images.
// ============================================================
__global__ void prep_kernel(WPtrs wp)
{
    const int node = blockIdx.x, tid = threadIdx.x;
    const NodeInfo& nd = c_nodes[node];

    {   // W1: [n*64, 128], NT=16, KT=4n
        const float* W = wp.w1[nd.gi] + (size_t)nd.row * nd.n * 64 * 128;
        uint4* dst = g_wbuf + (size_t)c_offs1[node] * 2048;
        const int tot = nd.n * 2048;
        for (int i = tid; i < tot; i += blockDim.x) {
            int lane = i & 31, idx = i >> 5, nt = idx & 15, kt = idx >> 4;
            int g = lane >> 2, t = lane & 3;
            int n = nt * 8 + g, k0 = kt * 16 + 2 * t;
            float a0 = W[(size_t)k0 * 128 + n],       a1 = W[(size_t)(k0 + 1) * 128 + n];
            float a2 = W[(size_t)(k0 + 8) * 128 + n], a3 = W[(size_t)(k0 + 9) * 128 + n];
            uint4 v;
            hilo2(a0, a1, v.x, v.z);
            hilo2(a2, a3, v.y, v.w);
            dst[i] = v;
        }
    }
    {   // W2: [128,128], NT=16, KT=8
        const float* W = wp.w2[nd.gi] + (size_t)nd.row * 128 * 128;
        uint4* dst = g_wbuf + W2OFF + (size_t)node * 4096;
        for (int i = tid; i < 4096; i += blockDim.x) {
            int lane = i & 31, idx = i >> 5, nt = idx & 15, kt = idx >> 4;
            int g = lane >> 2, t = lane & 3;
            int n = nt * 8 + g, k0 = kt * 16 + 2 * t;
            float a0 = W[(size_t)k0 * 128 + n],       a1 = W[(size_t)(k0 + 1) * 128 + n];
            float a2 = W[(size_t)(k0 + 8) * 128 + n], a3 = W[(size_t)(k0 + 9) * 128 + n];
            uint4 v;
            hilo2(a0, a1, v.x, v.z);
            hilo2(a2, a3, v.y, v.w);
            dst[i] = v;
        }
    }
    {   // W3: [128,64], NT=8, KT=8
        const float* W = wp.w3[nd.gi] + (size_t)nd.row * 128 * 64;
        uint4* dst = g_wbuf + W3OFF + (size_t)node * 2048;
        for (int i = tid; i < 2048; i += blockDim.x) {
            int lane = i & 31, idx = i >> 5, nt = idx & 7, kt = idx >> 3;
            int g = lane >> 2, t = lane & 3;
            int n = nt * 8 + g, k0 = kt * 16 + 2 * t;
            float a0 = W[(size_t)k0 * 64 + n],       a1 = W[(size_t)(k0 + 1) * 64 + n];
            float a2 = W[(size_t)(k0 + 8) * 64 + n], a3 = W[(size_t)(k0 + 9) * 64 + n];
            uint4 v;
            hilo2(a0, a1, v.x, v.z);
            hilo2(a2, a3, v.y, v.w);
            dst[i] = v;
        }
    }
}

// ============================================================
// main kernel: 4 warps/CTA, M=32/warp, TB=128. grid = (21, B/128).
// 2 CTAs/SM via __launch_bounds__(128, 2).
// Hidden spill smem (uint4): wid*1024 + ((m*8+kt)*2+plane)*32 + lane
//   plane 0 = hi, 1 = lo; lane-contiguous -> conflict-free. 64KB/CTA.
// ============================================================
#define HSPILL_BYTES 65536

__global__ void __launch_bounds__(128, 2)
mp_mma_kernel(const float* __restrict__ x, BPtrs bp, float* __restrict__ out)
{
    extern __shared__ uint4 hsp[];

    const int tid = threadIdx.x;
    const int wid = tid >> 5, lane = tid & 31;
    const int g = lane >> 2, t = lane & 3;
    const int node = blockIdx.x;
    const NodeInfo& nd = c_nodes[node];
    const int r0 = blockIdx.y * 128 + wid * 32 + g;   // block m: rows r0+16m / +8

    uint4* hslab = hsp + wid * 1024 + lane;

    float C[2][16][4];
    #pragma unroll
    for (int m = 0; m < 2; ++m)
        #pragma unroll
        for (int i = 0; i < 16; ++i)
            C[m][i][0] = C[m][i][1] = C[m][i][2] = C[m][i][3] = 0.f;

    // ---------------- layer 1 ----------------
    const uint4* __restrict__ W1b = g_wbuf + (size_t)c_offs1[node] * 2048 + lane;
    const int NK = nd.n * 4;

    float2 px[2][4];
    {
        const float* pb = x + (size_t)r0 * 1344 + nd.nb[0] * 64 + 2 * t;
        #pragma unroll
        for (int m = 0; m < 2; ++m) {
            const float* p = pb + (size_t)m * 16 * 1344;
            px[m][0] = *(const float2*)(p);
            px[m][1] = *(const float2*)(p + 8 * 1344);
            px[m][2] = *(const float2*)(p + 8);
            px[m][3] = *(const float2*)(p + 8 * 1344 + 8);
        }
    }

    for (int kg = 0; kg < NK; ++kg) {
        uint32_t ah[2][4], al[2][4];
        #pragma unroll
        for (int m = 0; m < 2; ++m) {
            hilo2(px[m][0].x, px[m][0].y, ah[m][0], al[m][0]);
            hilo2(px[m][1].x, px[m][1].y, ah[m][1], al[m][1]);
            hilo2(px[m][2].x, px[m][2].y, ah[m][2], al[m][2]);
            hilo2(px[m][3].x, px[m][3].y, ah[m][3], al[m][3]);
        }
        int nxt = kg + 1;
        if (nxt < NK) {   // prefetch next k-group's x during the MMAs
            const float* pb = x + (size_t)r0 * 1344 + nd.nb[nxt >> 2] * 64
                              + (nxt & 3) * 16 + 2 * t;
            #pragma unroll
            for (int m = 0; m < 2; ++m) {
                const float* p = pb + (size_t)m * 16 * 1344;
                px[m][0] = *(const float2*)(p);
                px[m][1] = *(const float2*)(p + 8 * 1344);
                px[m][2] = *(const float2*)(p + 8);
                px[m][3] = *(const float2*)(p + 8 * 1344 + 8);
            }
        }
        const uint4* wr = W1b + (size_t)kg * 512;
        #pragma unroll
        for (int nt = 0; nt < 16; ++nt) {
            uint4 b = wr[nt * 32];
            #pragma unroll
            for (int m = 0; m < 2; ++m) {
                mma_bf16(C[m][nt], ah[m], b.x, b.y);
                mma_bf16(C[m][nt], al[m], b.x, b.y);
                mma_bf16(C[m][nt], ah[m], b.z, b.w);
            }
        }
    }

    // epilogue 1: bias + relu -> smem spill (warp-private)
    {
        const float* B1 = bp.b1[nd.gi] + nd.row * 128;
        #pragma unroll
        for (int nt = 0; nt < 16; ++nt) {
            float2 bv = *(const float2*)(B1 + nt * 8 + 2 * t);
            const int kt = nt >> 1, h = nt & 1;
            #pragma unroll
            for (int m = 0; m < 2; ++m) {
                float v0 = fmaxf(C[m][nt][0] + bv.x, 0.f);
                float v1 = fmaxf(C[m][nt][1] + bv.y, 0.f);
                float v2 = fmaxf(C[m][nt][2] + bv.x, 0.f);
                float v3 = fmaxf(C[m][nt][3] + bv.y, 0.f);
                uint32_t h01, l01, h23, l23;
                hilo2(v0, v1, h01, l01);
                hilo2(v2, v3, h23, l23);
                uint2* dhi = (uint2*)(hslab + ((m * 8 + kt) * 2 + 0) * 32);
                uint2* dlo = (uint2*)(hslab + ((m * 8 + kt) * 2 + 1) * 32);
                dhi[h] = make_uint2(h01, h23);
                dlo[h] = make_uint2(l01, l23);
            }
        }
    }

    // ---------------- layer 2 ----------------
    #pragma unroll
    for (int m = 0; m < 2; ++m)
        #pragma unroll
        for (int i = 0; i < 16; ++i)
            C[m][i][0] = C[m][i][1] = C[m][i][2] = C[m][i][3] = 0.f;
    {
        const uint4* __restrict__ W2b = g_wbuf + W2OFF + (size_t)node * 4096 + lane;
        #pragma unroll
        for (int kt = 0; kt < 8; ++kt) {
            uint32_t Ah[2][4], Al[2][4];
            #pragma unroll
            for (int m = 0; m < 2; ++m) {
                uint4 hv = hslab[((m * 8 + kt) * 2 + 0) * 32];
                uint4 lv = hslab[((m * 8 + kt) * 2 + 1) * 32];
                Ah[m][0]=hv.x; Ah[m][1]=hv.y; Ah[m][2]=hv.z; Ah[m][3]=hv.w;
                Al[m][0]=lv.x; Al[m][1]=lv.y; Al[m][2]=lv.z; Al[m][3]=lv.w;
            }
            const uint4* wr = W2b + kt * 512;
            #pragma unroll
            for (int nt = 0; nt < 16; ++nt) {
                uint4 b = wr[nt * 32];
                #pragma unroll
                for (int m = 0; m < 2; ++m) {
                    mma_bf16(C[m][nt], Ah[m], b.x, b.y);
                    mma_bf16(C[m][nt], Al[m], b.x, b.y);
                    mma_bf16(C[m][nt], Ah[m], b.z, b.w);
                }
            }
        }
    }

    // epilogue 2 -> smem spill (overwrite)
    {
        const float* B2 = bp.b2[nd.gi] + nd.row * 128;
        #pragma unroll
        for (int nt = 0; nt < 16; ++nt) {
            float2 bv = *(const float2*)(B2 + nt * 8 + 2 * t);
            const int kt = nt >> 1, h = nt & 1;
            #pragma unroll
            for (int m = 0; m < 2; ++m) {
                float v0 = fmaxf(C[m][nt][0] + bv.x, 0.f);
                float v1 = fmaxf(C[m][nt][1] + bv.y, 0.f);
                float v2 = fmaxf(C[m][nt][2] + bv.x, 0.f);
                float v3 = fmaxf(C[m][nt][3] + bv.y, 0.f);
                uint32_t h01, l01, h23, l23;
                hilo2(v0, v1, h01, l01);
                hilo2(v2, v3, h23, l23);
                uint2* dhi = (uint2*)(hslab + ((m * 8 + kt) * 2 + 0) * 32);
                uint2* dlo = (uint2*)(hslab + ((m * 8 + kt) * 2 + 1) * 32);
                dhi[h] = make_uint2(h01, h23);
                dlo[h] = make_uint2(l01, l23);
            }
        }
    }

    // ---------------- layer 3 ----------------
    #pragma unroll
    for (int m = 0; m < 2; ++m)
        #pragma unroll
        for (int i = 0; i < 8; ++i)
            C[m][i][0] = C[m][i][1] = C[m][i][2] = C[m][i][3] = 0.f;
    {
        const uint4* __restrict__ W3b = g_wbuf + W3OFF + (size_t)node * 2048 + lane;
        #pragma unroll
        for (int kt = 0; kt < 8; ++kt) {
            uint32_t Ah[2][4], Al[2][4];
            #pragma unroll
            for (int m = 0; m < 2; ++m) {
                uint4 hv = hslab[((m * 8 + kt) * 2 + 0) * 32];
                uint4 lv = hslab[((m * 8 + kt) * 2 + 1) * 32];
                Ah[m][0]=hv.x; Ah[m][1]=hv.y; Ah[m][2]=hv.z; Ah[m][3]=hv.w;
                Al[m][0]=lv.x; Al[m][1]=lv.y; Al[m][2]=lv.z; Al[m][3]=lv.w;
            }
            const uint4* wr = W3b + kt * 256;
            #pragma unroll
            for (int nt = 0; nt < 8; ++nt) {
                uint4 b = wr[nt * 32];
                #pragma unroll
                for (int m = 0; m < 2; ++m) {
                    mma_bf16(C[m][nt], Ah[m], b.x, b.y);
                    mma_bf16(C[m][nt], Al[m], b.x, b.y);
                    mma_bf16(C[m][nt], Ah[m], b.z, b.w);
                }
            }
        }
    }

    // output epilogue
    {
        const float* B3 = bp.b3[nd.gi] + nd.row * 64;
        #pragma unroll
        for (int m = 0; m < 2; ++m) {
            float* o0 = out + (size_t)(r0 + m * 16) * 1344 + nd.out * 64 + 2 * t;
            #pragma unroll
            for (int nt = 0; nt < 8; ++nt) {
                float2 bv = *(const float2*)(B3 + nt * 8 + 2 * t);
                *(float2*)(o0 + nt * 8) =
                    make_float2(C[m][nt][0] + bv.x, C[m][nt][1] + bv.y);
                *(float2*)(o0 + nt * 8 + 8 * 1344) =
                    make_float2(C[m][nt][2] + bv.x, C[m][nt][3] + bv.y);
            }
        }
    }
}

// ============================================================
extern "C" void kernel_launch(void* const* d_in, const int* in_sizes, int n_in,
                              void* d_out, int out_size)
{
    const float* x = (const float*)d_in[0];
    WPtrs wp; BPtrs bp;
    for (int g = 0; g < 5; ++g) {
        wp.w1[g] = (const float*)d_in[1 + 6*g + 0];
        bp.b1[g] = (const float*)d_in[1 + 6*g + 1];
        wp.w2[g] = (const float*)d_in[1 + 6*g + 2];
        bp.b2[g] = (const float*)d_in[1 + 6*g + 3];
        wp.w3[g] = (const float*)d_in[1 + 6*g + 4];
        bp.b3[g] = (const float*)d_in[1 + 6*g + 5];
    }
    int B = in_sizes[0] / (21 * 64);

    prep_kernel<<<21, 256>>>(wp);

    cudaFuncSetAttribute(mp_mma_kernel,
                         cudaFuncAttributeMaxDynamicSharedMemorySize, HSPILL_BYTES);
    dim3 grid(21, B / 128);
    mp_mma_kernel<<<grid, 128, HSPILL_BYTES>>>(x, bp, (float*)d_out);
}